// round 14
// baseline (speedup 1.0000x reference)
#include <cuda_runtime.h>
#include <cuda_fp16.h>
#include <cstdint>

#define BSZ 8192
#define CDIM 128
#define DDIM 256
#define TILE 128
#define NTILE 64          // BSZ / TILE
#define NPAIRS 2080       // NTILE*(NTILE+1)/2

// ---------------- scratch (static device globals; no allocation) ----------------
__device__ unsigned g_se[(size_t)BSZ * BSZ];    // packed (sim fp16 | eud fp16); upper tiles only
__device__ __half g_lab_h[(size_t)BSZ * CDIM];  // pre-normalized labels, fp16
__device__ __half g_out_h[(size_t)BSZ * DDIM];  // outputs, fp16
__device__ float g_sq[BSZ];                     // ||fp16(output_i)||^2 (fp32 accum)
__device__ float2 g_part[(size_t)(2 * NTILE) * BSZ];  // per-(slot, row) partials, slot-major
__device__ float g_rowloss[BSZ];
__device__ unsigned g_smin_enc, g_smax_enc, g_emax_enc;

// monotone float <-> uint encoding so min/max reduce with integer atomics
__device__ __forceinline__ unsigned fenc(float f) {
    unsigned u = __float_as_uint(f);
    return (u & 0x80000000u) ? ~u : (u | 0x80000000u);
}
__device__ __forceinline__ float fdec(unsigned e) {
    unsigned u = (e & 0x80000000u) ? (e & 0x7FFFFFFFu) : ~e;
    return __uint_as_float(u);
}

// triangular pair decode: k in [0, NPAIRS) -> (a, b) with 0 <= a <= b < NTILE
__device__ __forceinline__ int tri_off(int a) { return a * NTILE - (a * (a - 1)) / 2; }
__device__ __forceinline__ void tri_decode(int k, int& a, int& b) {
    int aa = (int)((129.0f - sqrtf(16641.0f - 8.0f * (float)k)) * 0.5f);
    aa = max(0, min(63, aa));
    while (aa < 63 && tri_off(aa + 1) <= k) aa++;
    while (aa > 0 && tri_off(aa) > k) aa--;
    a = aa;
    b = aa + (k - tri_off(aa));
}

__device__ __forceinline__ uint32_t smem_u32(const void* p) {
    uint32_t a;
    asm("{ .reg .u64 t; cvta.to.shared.u64 t, %1; cvt.u32.u64 %0, t; }" : "=r"(a) : "l"(p));
    return a;
}
__device__ __forceinline__ uint4 ldsm_x4(uint32_t addr) {
    uint4 r;
    asm volatile("ldmatrix.sync.aligned.m8n8.x4.shared.b16 {%0,%1,%2,%3}, [%4];"
                 : "=r"(r.x), "=r"(r.y), "=r"(r.z), "=r"(r.w) : "r"(addr));
    return r;
}
__device__ __forceinline__ void mma16(float* c, uint4 a, uint32_t b0, uint32_t b1) {
    asm volatile(
        "mma.sync.aligned.m16n8k16.row.col.f32.f16.f16.f32 "
        "{%0,%1,%2,%3}, {%4,%5,%6,%7}, {%8,%9}, {%0,%1,%2,%3};"
        : "+f"(c[0]), "+f"(c[1]), "+f"(c[2]), "+f"(c[3])
        : "r"(a.x), "r"(a.y), "r"(a.z), "r"(a.w), "r"(b0), "r"(b1));
}
__device__ __forceinline__ float ex2f(float x) {
    float y;
    asm("ex2.approx.f32 %0, %1;" : "=f"(y) : "f"(x));
    return y;
}
__device__ __forceinline__ float sqrtaf(float x) {
    float y;
    asm("sqrt.approx.f32 %0, %1;" : "=f"(y) : "f"(x));
    return y;
}
__device__ __forceinline__ uint4 ldg_nc4(const void* p) {
    uint4 r;
    asm volatile("ld.global.nc.v4.u32 {%0,%1,%2,%3}, [%4];"
                 : "=r"(r.x), "=r"(r.y), "=r"(r.z), "=r"(r.w) : "l"(p));
    return r;
}
#define CP_ASYNC16(dst, src) \
    asm volatile("cp.async.cg.shared.global [%0], [%1], 16;" :: "r"(dst), "l"(src))
#define CP_COMMIT() asm volatile("cp.async.commit_group;" ::: "memory")
#define CP_WAIT(n)  asm volatile("cp.async.wait_group %0;" :: "n"(n) : "memory")

// ---------------- gram smem layout (bytes): 3 stages x 32KB + sq arrays ----------------
#define OFF_SQI   98304
#define OFF_SQJ   98816
#define SM_BYTES  99328

// copy one 128-row x 64-half tile into SW128-swizzled smem via cp.async
__device__ __forceinline__ void cpasync_tile(const __half* __restrict__ src, int ldh, int k0,
                                             uint32_t smem_dst, int tid) {
    #pragma unroll
    for (int it = 0; it < 4; it++) {
        int e = tid + 256 * it;                  // 0..1023 granules of 16B
        int row = e >> 3, gq = e & 7;
        const __half* g = src + (size_t)row * ldh + k0 + gq * 8;
        uint32_t bo = (uint32_t)(row * 128 + gq * 16);
        uint32_t dst = smem_dst + (bo ^ ((bo >> 3) & 0x70));
        CP_ASYNC16(dst, g);
    }
}

__device__ __forceinline__ unsigned pack_se(unsigned simlo16, float e) {
    unsigned eh = (unsigned)__half_as_ushort(__float2half_rn(e));
    return (simlo16 & 0xFFFFu) | (eh << 16);
}

// ---------------- kernel 1: per-row prep (absorbs init; warp-per-row, no block syncs) ----------------
__global__ __launch_bounds__(256) void rowprep_kernel(const float* __restrict__ outputs,
                                                      const float* __restrict__ labels) {
    if (blockIdx.x == 0 && threadIdx.x == 0) {
        g_smin_enc = fenc(3.4e38f);
        g_smax_enc = fenc(-3.4e38f);
        g_emax_enc = fenc(0.0f);
    }

    const int row = blockIdx.x * 8 + (threadIdx.x >> 5);
    const int lane = threadIdx.x & 31;

    // labels: 4 elements per lane
    float l[4];
    float lsum = 0.0f;
    #pragma unroll
    for (int x = 0; x < 4; x++) {
        l[x] = labels[(size_t)row * CDIM + lane + 32 * x];
        lsum += l[x] * l[x];
    }
    #pragma unroll
    for (int off = 16; off; off >>= 1) lsum += __shfl_xor_sync(0xffffffffu, lsum, off);
    float invn = 1.0f / (sqrtf(lsum) + 1e-12f);
    #pragma unroll
    for (int x = 0; x < 4; x++)
        g_lab_h[(size_t)row * CDIM + lane + 32 * x] = __float2half(l[x] * invn);

    // outputs: 8 elements per lane; sq from rounded values
    float osum = 0.0f;
    #pragma unroll
    for (int x = 0; x < 8; x++) {
        float o = outputs[(size_t)row * DDIM + lane + 32 * x];
        __half h = __float2half(o);
        g_out_h[(size_t)row * DDIM + lane + 32 * x] = h;
        float f = __half2float(h);
        osum += f * f;
    }
    #pragma unroll
    for (int off = 16; off; off >>= 1) osum += __shfl_xor_sync(0xffffffffu, osum, off);
    if (lane == 0) g_sq[row] = osum;
}

// ---------------- kernel 2: fp16 mma fused grams, race-free 3-stage pipeline ----------------
__global__ __launch_bounds__(256, 2) void gram_mma() {
    int bi, bj;
    tri_decode(blockIdx.x, bi, bj);
    extern __shared__ float sm[];
    const uint32_t sb = smem_u32(sm);
    float* s_sqi = (float*)((char*)sm + OFF_SQI);
    float* s_sqj = (float*)((char*)sm + OFF_SQJ);

    const int tid = threadIdx.x;
    const int wid = tid >> 5, lane = tid & 31;
    const int warp_m = wid >> 2, warp_n = wid & 3;
    const int g = lane >> 2, tig = lane & 3;
    const int i0 = bi * TILE, j0 = bj * TILE;

    if (tid < 128) {
        s_sqi[tid] = g_sq[i0 + tid];
        s_sqj[tid] = g_sq[j0 + tid];
    }

    // ldmatrix per-lane address precompute (byte offsets within 128x64h tile, 128B rows)
    const int laneA_row = lane & 15;
    const uint32_t baseA = (uint32_t)(((warp_m * 64 + laneA_row) << 7) + ((lane >> 4) << 4));
    const uint32_t xorA = (uint32_t)((laneA_row & 7) << 4);
    const int rowB = warp_n * 32 + ((lane >> 4) << 3) + (lane & 7);
    const uint32_t baseB = (uint32_t)((rowB << 7) + (((lane >> 3) & 1) << 4));
    const uint32_t xorB = (uint32_t)((rowB & 7) << 4);

    float c[4][4][4];
    #pragma unroll
    for (int mf = 0; mf < 4; mf++)
        #pragma unroll
        for (int nf = 0; nf < 4; nf++)
            #pragma unroll
            for (int r = 0; r < 4; r++) c[mf][nf][r] = 0.0f;

    unsigned simh[32];   // register-resident sim tile (fp16x2)

    const __half* AiL = g_lab_h + (size_t)i0 * CDIM;
    const __half* BjL = g_lab_h + (size_t)j0 * CDIM;
    const __half* AiO = g_out_h + (size_t)i0 * DDIM;
    const __half* BjO = g_out_h + (size_t)j0 * DDIM;

    // preload chunks 0 and 1 (separate commit groups)
    cpasync_tile(AiL, CDIM, 0, sb, tid);
    cpasync_tile(BjL, CDIM, 0, sb + 16384, tid);
    CP_COMMIT();
    cpasync_tile(AiL, CDIM, 64, sb + 32768, tid);
    cpasync_tile(BjL, CDIM, 64, sb + 32768 + 16384, tid);
    CP_COMMIT();

    // merged 6-chunk pipeline: chunks 0-1 = label gram, 2-5 = output gram
    // order per iteration: WAIT(ch) -> sync -> prefetch(ch+2) -> compute(ch)
    #pragma unroll 1
    for (int ch = 0; ch < 6; ch++) {
        if (ch < 5) CP_WAIT(1);
        else        CP_WAIT(0);
        __syncthreads();

        if (ch + 2 < 6) {
            int nx = ch + 2;
            uint32_t nb = sb + (nx % 3) * 32768;
            if (nx < 2) {
                cpasync_tile(AiL, CDIM, nx * 64, nb, tid);
                cpasync_tile(BjL, CDIM, nx * 64, nb + 16384, tid);
            } else {
                cpasync_tile(AiO, DDIM, (nx - 2) * 64, nb, tid);
                cpasync_tile(BjO, DDIM, (nx - 2) * 64, nb + 16384, tid);
            }
            CP_COMMIT();
        }

        uint32_t sA = sb + (ch % 3) * 32768;
        uint32_t sB = sA + 16384;
        #pragma unroll
        for (int ks = 0; ks < 4; ks++) {
            uint4 a[4];
            #pragma unroll
            for (int mf = 0; mf < 4; mf++)
                a[mf] = ldsm_x4(sA + ((baseA + mf * 2048 + ks * 32) ^ xorA));
            uint4 b0 = ldsm_x4(sB + ((baseB + ks * 32) ^ xorB));
            uint4 b1 = ldsm_x4(sB + ((baseB + 2048 + ks * 32) ^ xorB));
            #pragma unroll
            for (int mf = 0; mf < 4; mf++) {
                mma16(c[mf][0], a[mf], b0.x, b0.y);
                mma16(c[mf][1], a[mf], b0.z, b0.w);
                mma16(c[mf][2], a[mf], b1.x, b1.y);
                mma16(c[mf][3], a[mf], b1.z, b1.w);
            }
        }
        if (ch == 1) {
            // epilogue A (overlaps in-flight copies): pack sim to regs, min/max, zero accums
            float lmin = 3.4e38f, lmax = -3.4e38f;
            #pragma unroll
            for (int mf = 0; mf < 4; mf++) {
                #pragma unroll
                for (int nf = 0; nf < 4; nf++) {
                    float v0 = c[mf][nf][0], v1 = c[mf][nf][1];
                    float v2 = c[mf][nf][2], v3 = c[mf][nf][3];
                    lmin = fminf(lmin, fminf(fminf(v0, v1), fminf(v2, v3)));
                    lmax = fmaxf(lmax, fmaxf(fmaxf(v0, v1), fmaxf(v2, v3)));
                    int idx0 = (mf * 4 + nf) * 2;
                    __half2 h01 = __floats2half2_rn(v0, v1);
                    __half2 h23 = __floats2half2_rn(v2, v3);
                    simh[idx0]     = *(unsigned*)&h01;
                    simh[idx0 + 1] = *(unsigned*)&h23;
                    c[mf][nf][0] = 0.0f; c[mf][nf][1] = 0.0f;
                    c[mf][nf][2] = 0.0f; c[mf][nf][3] = 0.0f;
                }
            }
            #pragma unroll
            for (int off = 16; off; off >>= 1) {
                lmin = fminf(lmin, __shfl_xor_sync(0xffffffffu, lmin, off));
                lmax = fmaxf(lmax, __shfl_xor_sync(0xffffffffu, lmax, off));
            }
            if (lane == 0) {
                atomicMin(&g_smin_enc, fenc(lmin));
                atomicMax(&g_smax_enc, fenc(lmax));
            }
        }
    }

    // epilogue B: eud + packed (sim|eud) store, upper tile only
    {
        float lemax = 0.0f;
        #pragma unroll
        for (int mf = 0; mf < 4; mf++) {
            int il = warp_m * 64 + mf * 16 + g;
            float q0 = s_sqi[il], q1 = s_sqi[il + 8];
            #pragma unroll
            for (int nf = 0; nf < 4; nf++) {
                int jl = warp_n * 32 + nf * 8 + 2 * tig;
                float r0 = s_sqj[jl], r1 = s_sqj[jl + 1];
                float d0 = q0 + r0 - 2.0f * c[mf][nf][0];
                float d1 = q0 + r1 - 2.0f * c[mf][nf][1];
                float d2_ = q1 + r0 - 2.0f * c[mf][nf][2];
                float d3 = q1 + r1 - 2.0f * c[mf][nf][3];
                float v0 = (d0 > 0.0f) ? sqrtaf(d0) : 0.0f;
                float v1 = (d1 > 0.0f) ? sqrtaf(d1) : 0.0f;
                float v2 = (d2_ > 0.0f) ? sqrtaf(d2_) : 0.0f;
                float v3 = (d3 > 0.0f) ? sqrtaf(d3) : 0.0f;
                if (i0 + il == j0 + jl) v0 = 0.0f;
                if (i0 + il == j0 + jl + 1) v1 = 0.0f;
                if (i0 + il + 8 == j0 + jl) v2 = 0.0f;
                if (i0 + il + 8 == j0 + jl + 1) v3 = 0.0f;
                lemax = fmaxf(lemax, fmaxf(fmaxf(v0, v1), fmaxf(v2, v3)));

                int idx0 = (mf * 4 + nf) * 2;
                unsigned sp01 = simh[idx0];
                unsigned sp23 = simh[idx0 + 1];
                unsigned u0 = pack_se(sp01, v0);
                unsigned u1 = pack_se(sp01 >> 16, v1);
                unsigned u2 = pack_se(sp23, v2);
                unsigned u3 = pack_se(sp23 >> 16, v3);

                *(uint2*)&g_se[(size_t)(i0 + il) * BSZ + j0 + jl]     = make_uint2(u0, u1);
                *(uint2*)&g_se[(size_t)(i0 + il + 8) * BSZ + j0 + jl] = make_uint2(u2, u3);
            }
        }
        #pragma unroll
        for (int off = 16; off; off >>= 1)
            lemax = fmaxf(lemax, __shfl_xor_sync(0xffffffffu, lemax, off));
        if (lane == 0) atomicMax(&g_emax_enc, fenc(lemax));
    }
}

// ---------------- kernel 3: half-tile loss (2 blocks per tile, 64 rows each) ----------------
// slot layout in g_part: row-partials of pair (bi,bj) -> slot 2*bj (both halves, disjoint rows)
//                        col-partials of pair (bi,bj), half h -> slot 2*bi+h (full j range)
__global__ __launch_bounds__(256, 6) void loss_tile_kernel() {
    const int pair = (int)blockIdx.x >> 1;
    const int h = (int)blockIdx.x & 1;
    int bi, bj;
    tri_decode(pair, bi, bj);
    const int i0 = bi * TILE, j0 = bj * TILE;
    const int rb = i0 + h * 64;
    const int t = threadIdx.x;
    const int w = t >> 5, lane = t & 31;
    const int cg = lane & 15;        // 8-column group: cols cg*8 .. cg*8+7
    const int rhalf = lane >> 4;     // row within the pair

    const float L2E = 1.4426950408889634f;
    const float smin = fdec(g_smin_enc);
    const float smax = fdec(g_smax_enc);
    const float emax = fdec(g_emax_enc);
    const float c1 = L2E / (smax - smin);
    const float c0 = -smin * c1;
    const float c2 = L2E / emax;
    const float sthr = smin + 0.5f * (smax - smin);

    __shared__ float2 scol[8][128];

    float cp[8] = {0, 0, 0, 0, 0, 0, 0, 0};
    float cn[8] = {0, 0, 0, 0, 0, 0, 0, 0};
    float rp[4], rn[4];

    const char* base0 = (const char*)&g_se[(size_t)(rb + w * 8 + rhalf) * BSZ + j0 + cg * 8];
    const size_t rstep = (size_t)2 * BSZ * 4;   // 2 rows per iteration, 4B per element

    uint4 v0 = ldg_nc4(base0);
    uint4 v1 = ldg_nc4(base0 + 16);

    #pragma unroll
    for (int it = 0; it < 4; it++) {
        uint4 a0 = v0, a1 = v1;
        if (it < 3) {
            const char* nb = base0 + (size_t)(it + 1) * rstep;
            v0 = ldg_nc4(nb);
            v1 = ldg_nc4(nb + 16);
        }
        unsigned uu[8] = {a0.x, a0.y, a0.z, a0.w, a1.x, a1.y, a1.z, a1.w};
        float p = 0.0f, n = 0.0f;
        #pragma unroll
        for (int x = 0; x < 8; x++) {
            float2 f = __half22float2(*(__half2*)&uu[x]);   // f.x = sim, f.y = eud
            float d = fmaf(f.y, c2, fmaf(f.x, c1, c0));
            bool pos = f.x > sthr;
            float val = ex2f(pos ? d : (L2E - d));
            float vp = pos ? val : 0.0f;
            float vn = pos ? 0.0f : val;
            p += vp; n += vn;
            cp[x] += vp; cn[x] += vn;
        }
        rp[it] = p;
        rn[it] = n;
    }

    // batched row reductions: 8 independent shfl chains pipeline through the unit
    #pragma unroll
    for (int off = 8; off; off >>= 1) {
        #pragma unroll
        for (int it = 0; it < 4; it++) {
            rp[it] += __shfl_xor_sync(0xffffffffu, rp[it], off);
            rn[it] += __shfl_xor_sync(0xffffffffu, rn[it], off);
        }
    }
    if (cg == 0) {
        #pragma unroll
        for (int it = 0; it < 4; it++) {
            int row = rb + w * 8 + it * 2 + rhalf;
            g_part[(size_t)(2 * bj) * BSZ + row] = make_float2(rp[it], rn[it]);
        }
    }

    // fold the two row-halves' column partials, then cross-warp reduce in smem
    #pragma unroll
    for (int x = 0; x < 8; x++) {
        cp[x] += __shfl_xor_sync(0xffffffffu, cp[x], 16);
        cn[x] += __shfl_xor_sync(0xffffffffu, cn[x], 16);
    }
    if (rhalf == 0) {
        #pragma unroll
        for (int x = 0; x < 8; x++) scol[w][cg * 8 + x] = make_float2(cp[x], cn[x]);
    }
    __syncthreads();
    if (bi != bj && t < 128) {
        float p = 0.0f, n = 0.0f;
        #pragma unroll
        for (int ww = 0; ww < 8; ww++) {
            float2 v = scol[ww][t];
            p += v.x; n += v.y;
        }
        g_part[(size_t)(2 * bi + h) * BSZ + j0 + t] = make_float2(p, n);
    }
}

// ---------------- kernel 4: structure-aware per-row reduce ----------------
// for row in tile tr: slots 2s always valid; slots 2s+1 valid only for s < tr
__global__ __launch_bounds__(256) void rowreduce_kernel() {
    const int w = threadIdx.x >> 5, lane = threadIdx.x & 31;
    const int row = blockIdx.x * 32 + lane;
    const int tr = blockIdx.x >> 2;   // tile of these 32 rows

    float P = 0.0f, N = 0.0f;
    #pragma unroll
    for (int q = 0; q < 8; q++) {
        int s = w * 8 + q;
        float2 v = g_part[(size_t)(2 * s) * BSZ + row];
        P += v.x; N += v.y;
        if (s < tr) {
            float2 u = g_part[(size_t)(2 * s + 1) * BSZ + row];
            P += u.x; N += u.y;
        }
    }

    __shared__ float2 sc[8][32];
    sc[w][lane] = make_float2(P, N);
    __syncthreads();
    if (w == 0) {
        float Pt = 0.0f, Nt = 0.0f;
        #pragma unroll
        for (int ww = 0; ww < 8; ww++) {
            float2 u = sc[ww][lane];
            Pt += u.x; Nt += u.y;
        }
        float lp = fmaxf(logf(Pt), 0.0f);   // log(0) = -inf -> clamped to 0
        float ln = fmaxf(logf(Nt), 0.0f);
        g_rowloss[row] = lp + ln;
    }
}

// ---------------- kernel 5: deterministic final mean ----------------
__global__ __launch_bounds__(256) void final_kernel(float* __restrict__ out) {
    __shared__ float s[256];
    const int t = threadIdx.x;
    float a = 0.0f;
    for (int i = t; i < BSZ; i += 256) a += g_rowloss[i];
    s[t] = a;
    __syncthreads();
    #pragma unroll
    for (int o = 128; o; o >>= 1) {
        if (t < o) s[t] += s[t + o];
        __syncthreads();
    }
    if (t == 0) out[0] = s[0] * (1.0f / (float)BSZ);
}

// ---------------- launch ----------------
extern "C" void kernel_launch(void* const* d_in, const int* in_sizes, int n_in,
                              void* d_out, int out_size) {
    const float* outputs = (const float*)d_in[0];
    const float* labels  = (const float*)d_in[1];
    if (n_in >= 2 && in_sizes[0] == BSZ * CDIM && in_sizes[1] == BSZ * DDIM) {
        const float* tmp = outputs; outputs = labels; labels = tmp;
    }
    float* out = (float*)d_out;

    cudaFuncSetAttribute(gram_mma, cudaFuncAttributeMaxDynamicSharedMemorySize, SM_BYTES);

    rowprep_kernel<<<BSZ / 8, 256>>>(outputs, labels);
    gram_mma<<<NPAIRS, 256, SM_BYTES>>>();
    loss_tile_kernel<<<2 * NPAIRS, 256>>>();
    rowreduce_kernel<<<BSZ / 32, 256>>>();
    final_kernel<<<1, 256>>>(out);
}

// round 15
// speedup vs baseline: 1.0084x; 1.0084x over previous
#include <cuda_runtime.h>
#include <cuda_fp16.h>
#include <cstdint>

#define BSZ 8192
#define CDIM 128
#define DDIM 256
#define TILE 128
#define NTILE 64          // BSZ / TILE
#define NPAIRS 2080       // NTILE*(NTILE+1)/2

// ---------------- scratch (static device globals; no allocation) ----------------
__device__ unsigned g_se[(size_t)BSZ * BSZ];    // packed (sim fp16 | eud fp16); upper tiles only
__device__ __half g_lab_h[(size_t)BSZ * CDIM];  // pre-normalized labels, fp16
__device__ __half g_out_h[(size_t)BSZ * DDIM];  // outputs, fp16
__device__ float g_sq[BSZ];                     // ||fp16(output_i)||^2 (fp32 accum)
__device__ float2 g_part[(size_t)NTILE * BSZ];  // per-(tile, row) partial sums (TILE-MAJOR)
__device__ float g_rowloss[BSZ];
__device__ unsigned g_smin_enc, g_smax_enc, g_emax_enc;
__device__ unsigned g_ticket;

// monotone float <-> uint encoding so min/max reduce with integer atomics
__device__ __forceinline__ unsigned fenc(float f) {
    unsigned u = __float_as_uint(f);
    return (u & 0x80000000u) ? ~u : (u | 0x80000000u);
}
__device__ __forceinline__ float fdec(unsigned e) {
    unsigned u = (e & 0x80000000u) ? (e & 0x7FFFFFFFu) : ~e;
    return __uint_as_float(u);
}

// triangular pair decode: k in [0, NPAIRS) -> (a, b) with 0 <= a <= b < NTILE
__device__ __forceinline__ int tri_off(int a) { return a * NTILE - (a * (a - 1)) / 2; }
__device__ __forceinline__ void tri_decode(int k, int& a, int& b) {
    int aa = (int)((129.0f - sqrtf(16641.0f - 8.0f * (float)k)) * 0.5f);
    aa = max(0, min(63, aa));
    while (aa < 63 && tri_off(aa + 1) <= k) aa++;
    while (aa > 0 && tri_off(aa) > k) aa--;
    a = aa;
    b = aa + (k - tri_off(aa));
}

__device__ __forceinline__ uint32_t smem_u32(const void* p) {
    uint32_t a;
    asm("{ .reg .u64 t; cvta.to.shared.u64 t, %1; cvt.u32.u64 %0, t; }" : "=r"(a) : "l"(p));
    return a;
}
__device__ __forceinline__ uint4 ldsm_x4(uint32_t addr) {
    uint4 r;
    asm volatile("ldmatrix.sync.aligned.m8n8.x4.shared.b16 {%0,%1,%2,%3}, [%4];"
                 : "=r"(r.x), "=r"(r.y), "=r"(r.z), "=r"(r.w) : "r"(addr));
    return r;
}
__device__ __forceinline__ void mma16(float* c, uint4 a, uint32_t b0, uint32_t b1) {
    asm volatile(
        "mma.sync.aligned.m16n8k16.row.col.f32.f16.f16.f32 "
        "{%0,%1,%2,%3}, {%4,%5,%6,%7}, {%8,%9}, {%0,%1,%2,%3};"
        : "+f"(c[0]), "+f"(c[1]), "+f"(c[2]), "+f"(c[3])
        : "r"(a.x), "r"(a.y), "r"(a.z), "r"(a.w), "r"(b0), "r"(b1));
}
__device__ __forceinline__ float ex2f(float x) {
    float y;
    asm("ex2.approx.f32 %0, %1;" : "=f"(y) : "f"(x));
    return y;
}
__device__ __forceinline__ float sqrtaf(float x) {
    float y;
    asm("sqrt.approx.f32 %0, %1;" : "=f"(y) : "f"(x));
    return y;
}
__device__ __forceinline__ uint4 ldg_nc4(const void* p) {
    uint4 r;
    asm volatile("ld.global.nc.v4.u32 {%0,%1,%2,%3}, [%4];"
                 : "=r"(r.x), "=r"(r.y), "=r"(r.z), "=r"(r.w) : "l"(p));
    return r;
}
#define CP_ASYNC16(dst, src) \
    asm volatile("cp.async.cg.shared.global [%0], [%1], 16;" :: "r"(dst), "l"(src))
#define CP_COMMIT() asm volatile("cp.async.commit_group;" ::: "memory")
#define CP_WAIT(n)  asm volatile("cp.async.wait_group %0;" :: "n"(n) : "memory")

// ---------------- gram smem layout (bytes): 3 stages x 32KB + sq arrays ----------------
#define OFF_SQI   98304
#define OFF_SQJ   98816
#define SM_BYTES  99328

// copy one 128-row x 64-half tile into SW128-swizzled smem via cp.async
__device__ __forceinline__ void cpasync_tile(const __half* __restrict__ src, int ldh, int k0,
                                             uint32_t smem_dst, int tid) {
    #pragma unroll
    for (int it = 0; it < 4; it++) {
        int e = tid + 256 * it;                  // 0..1023 granules of 16B
        int row = e >> 3, gq = e & 7;
        const __half* g = src + (size_t)row * ldh + k0 + gq * 8;
        uint32_t bo = (uint32_t)(row * 128 + gq * 16);
        uint32_t dst = smem_dst + (bo ^ ((bo >> 3) & 0x70));
        CP_ASYNC16(dst, g);
    }
}

__device__ __forceinline__ unsigned pack_se(unsigned simlo16, float e) {
    unsigned eh = (unsigned)__half_as_ushort(__float2half_rn(e));
    return (simlo16 & 0xFFFFu) | (eh << 16);
}

// ---------------- kernel 1: per-row prep (absorbs init; warp-per-row, no block syncs) ----------------
__global__ __launch_bounds__(256) void rowprep_kernel(const float* __restrict__ outputs,
                                                      const float* __restrict__ labels) {
    if (blockIdx.x == 0 && threadIdx.x == 0) {
        g_smin_enc = fenc(3.4e38f);
        g_smax_enc = fenc(-3.4e38f);
        g_emax_enc = fenc(0.0f);
        g_ticket = 0u;
    }

    const int row = blockIdx.x * 8 + (threadIdx.x >> 5);
    const int lane = threadIdx.x & 31;

    // labels: 4 elements per lane
    float l[4];
    float lsum = 0.0f;
    #pragma unroll
    for (int x = 0; x < 4; x++) {
        l[x] = labels[(size_t)row * CDIM + lane + 32 * x];
        lsum += l[x] * l[x];
    }
    #pragma unroll
    for (int off = 16; off; off >>= 1) lsum += __shfl_xor_sync(0xffffffffu, lsum, off);
    float invn = 1.0f / (sqrtf(lsum) + 1e-12f);
    #pragma unroll
    for (int x = 0; x < 4; x++)
        g_lab_h[(size_t)row * CDIM + lane + 32 * x] = __float2half(l[x] * invn);

    // outputs: 8 elements per lane; sq from rounded values
    float osum = 0.0f;
    #pragma unroll
    for (int x = 0; x < 8; x++) {
        float o = outputs[(size_t)row * DDIM + lane + 32 * x];
        __half h = __float2half(o);
        g_out_h[(size_t)row * DDIM + lane + 32 * x] = h;
        float f = __half2float(h);
        osum += f * f;
    }
    #pragma unroll
    for (int off = 16; off; off >>= 1) osum += __shfl_xor_sync(0xffffffffu, osum, off);
    if (lane == 0) g_sq[row] = osum;
}

// ---------------- kernel 2: fp16 mma fused grams, race-free 3-stage pipeline ----------------
__global__ __launch_bounds__(256, 2) void gram_mma() {
    int bi, bj;
    tri_decode(blockIdx.x, bi, bj);
    extern __shared__ float sm[];
    const uint32_t sb = smem_u32(sm);
    float* s_sqi = (float*)((char*)sm + OFF_SQI);
    float* s_sqj = (float*)((char*)sm + OFF_SQJ);

    const int tid = threadIdx.x;
    const int wid = tid >> 5, lane = tid & 31;
    const int warp_m = wid >> 2, warp_n = wid & 3;
    const int g = lane >> 2, tig = lane & 3;
    const int i0 = bi * TILE, j0 = bj * TILE;

    if (tid < 128) {
        s_sqi[tid] = g_sq[i0 + tid];
        s_sqj[tid] = g_sq[j0 + tid];
    }

    // ldmatrix per-lane address precompute (byte offsets within 128x64h tile, 128B rows)
    const int laneA_row = lane & 15;
    const uint32_t baseA = (uint32_t)(((warp_m * 64 + laneA_row) << 7) + ((lane >> 4) << 4));
    const uint32_t xorA = (uint32_t)((laneA_row & 7) << 4);
    const int rowB = warp_n * 32 + ((lane >> 4) << 3) + (lane & 7);
    const uint32_t baseB = (uint32_t)((rowB << 7) + (((lane >> 3) & 1) << 4));
    const uint32_t xorB = (uint32_t)((rowB & 7) << 4);

    float c[4][4][4];
    #pragma unroll
    for (int mf = 0; mf < 4; mf++)
        #pragma unroll
        for (int nf = 0; nf < 4; nf++)
            #pragma unroll
            for (int r = 0; r < 4; r++) c[mf][nf][r] = 0.0f;

    unsigned simh[32];   // register-resident sim tile (fp16x2)

    const __half* AiL = g_lab_h + (size_t)i0 * CDIM;
    const __half* BjL = g_lab_h + (size_t)j0 * CDIM;
    const __half* AiO = g_out_h + (size_t)i0 * DDIM;
    const __half* BjO = g_out_h + (size_t)j0 * DDIM;

    // preload chunks 0 and 1 (separate commit groups)
    cpasync_tile(AiL, CDIM, 0, sb, tid);
    cpasync_tile(BjL, CDIM, 0, sb + 16384, tid);
    CP_COMMIT();
    cpasync_tile(AiL, CDIM, 64, sb + 32768, tid);
    cpasync_tile(BjL, CDIM, 64, sb + 32768 + 16384, tid);
    CP_COMMIT();

    // merged 6-chunk pipeline: chunks 0-1 = label gram, 2-5 = output gram
    // order per iteration: WAIT(ch) -> sync -> prefetch(ch+2) -> compute(ch)
    #pragma unroll 1
    for (int ch = 0; ch < 6; ch++) {
        if (ch < 5) CP_WAIT(1);
        else        CP_WAIT(0);
        __syncthreads();

        if (ch + 2 < 6) {
            int nx = ch + 2;
            uint32_t nb = sb + (nx % 3) * 32768;
            if (nx < 2) {
                cpasync_tile(AiL, CDIM, nx * 64, nb, tid);
                cpasync_tile(BjL, CDIM, nx * 64, nb + 16384, tid);
            } else {
                cpasync_tile(AiO, DDIM, (nx - 2) * 64, nb, tid);
                cpasync_tile(BjO, DDIM, (nx - 2) * 64, nb + 16384, tid);
            }
            CP_COMMIT();
        }

        uint32_t sA = sb + (ch % 3) * 32768;
        uint32_t sB = sA + 16384;
        #pragma unroll
        for (int ks = 0; ks < 4; ks++) {
            uint4 a[4];
            #pragma unroll
            for (int mf = 0; mf < 4; mf++)
                a[mf] = ldsm_x4(sA + ((baseA + mf * 2048 + ks * 32) ^ xorA));
            uint4 b0 = ldsm_x4(sB + ((baseB + ks * 32) ^ xorB));
            uint4 b1 = ldsm_x4(sB + ((baseB + 2048 + ks * 32) ^ xorB));
            #pragma unroll
            for (int mf = 0; mf < 4; mf++) {
                mma16(c[mf][0], a[mf], b0.x, b0.y);
                mma16(c[mf][1], a[mf], b0.z, b0.w);
                mma16(c[mf][2], a[mf], b1.x, b1.y);
                mma16(c[mf][3], a[mf], b1.z, b1.w);
            }
        }
        if (ch == 1) {
            // epilogue A (overlaps in-flight copies): pack sim to regs, min/max, zero accums
            float lmin = 3.4e38f, lmax = -3.4e38f;
            #pragma unroll
            for (int mf = 0; mf < 4; mf++) {
                #pragma unroll
                for (int nf = 0; nf < 4; nf++) {
                    float v0 = c[mf][nf][0], v1 = c[mf][nf][1];
                    float v2 = c[mf][nf][2], v3 = c[mf][nf][3];
                    lmin = fminf(lmin, fminf(fminf(v0, v1), fminf(v2, v3)));
                    lmax = fmaxf(lmax, fmaxf(fmaxf(v0, v1), fmaxf(v2, v3)));
                    int idx0 = (mf * 4 + nf) * 2;
                    __half2 h01 = __floats2half2_rn(v0, v1);
                    __half2 h23 = __floats2half2_rn(v2, v3);
                    simh[idx0]     = *(unsigned*)&h01;
                    simh[idx0 + 1] = *(unsigned*)&h23;
                    c[mf][nf][0] = 0.0f; c[mf][nf][1] = 0.0f;
                    c[mf][nf][2] = 0.0f; c[mf][nf][3] = 0.0f;
                }
            }
            #pragma unroll
            for (int off = 16; off; off >>= 1) {
                lmin = fminf(lmin, __shfl_xor_sync(0xffffffffu, lmin, off));
                lmax = fmaxf(lmax, __shfl_xor_sync(0xffffffffu, lmax, off));
            }
            if (lane == 0) {
                atomicMin(&g_smin_enc, fenc(lmin));
                atomicMax(&g_smax_enc, fenc(lmax));
            }
        }
    }

    // epilogue B: eud + packed (sim|eud) store, upper tile only
    {
        float lemax = 0.0f;
        #pragma unroll
        for (int mf = 0; mf < 4; mf++) {
            int il = warp_m * 64 + mf * 16 + g;
            float q0 = s_sqi[il], q1 = s_sqi[il + 8];
            #pragma unroll
            for (int nf = 0; nf < 4; nf++) {
                int jl = warp_n * 32 + nf * 8 + 2 * tig;
                float r0 = s_sqj[jl], r1 = s_sqj[jl + 1];
                float d0 = q0 + r0 - 2.0f * c[mf][nf][0];
                float d1 = q0 + r1 - 2.0f * c[mf][nf][1];
                float d2_ = q1 + r0 - 2.0f * c[mf][nf][2];
                float d3 = q1 + r1 - 2.0f * c[mf][nf][3];
                float v0 = (d0 > 0.0f) ? sqrtaf(d0) : 0.0f;
                float v1 = (d1 > 0.0f) ? sqrtaf(d1) : 0.0f;
                float v2 = (d2_ > 0.0f) ? sqrtaf(d2_) : 0.0f;
                float v3 = (d3 > 0.0f) ? sqrtaf(d3) : 0.0f;
                if (i0 + il == j0 + jl) v0 = 0.0f;
                if (i0 + il == j0 + jl + 1) v1 = 0.0f;
                if (i0 + il + 8 == j0 + jl) v2 = 0.0f;
                if (i0 + il + 8 == j0 + jl + 1) v3 = 0.0f;
                lemax = fmaxf(lemax, fmaxf(fmaxf(v0, v1), fmaxf(v2, v3)));

                int idx0 = (mf * 4 + nf) * 2;
                unsigned sp01 = simh[idx0];
                unsigned sp23 = simh[idx0 + 1];
                unsigned u0 = pack_se(sp01, v0);
                unsigned u1 = pack_se(sp01 >> 16, v1);
                unsigned u2 = pack_se(sp23, v2);
                unsigned u3 = pack_se(sp23 >> 16, v3);

                *(uint2*)&g_se[(size_t)(i0 + il) * BSZ + j0 + jl]     = make_uint2(u0, u1);
                *(uint2*)&g_se[(size_t)(i0 + il + 8) * BSZ + j0 + jl] = make_uint2(u2, u3);
            }
        }
        #pragma unroll
        for (int off = 16; off; off >>= 1)
            lemax = fmaxf(lemax, __shfl_xor_sync(0xffffffffu, lemax, off));
        if (lane == 0) atomicMax(&g_emax_enc, fenc(lemax));
    }
}

// ---------------- kernel 3: tile loss — batched shfl reductions, prefetched loads ----------------
__global__ __launch_bounds__(256, 4) void loss_tile_kernel() {
    int bi, bj;
    tri_decode((int)blockIdx.x, bi, bj);
    const int i0 = bi * TILE, j0 = bj * TILE;
    const int t = threadIdx.x;
    const int w = t >> 5, lane = t & 31;
    const int cg = lane & 15;        // 8-column group: cols cg*8 .. cg*8+7
    const int rhalf = lane >> 4;     // row within the pair

    const float L2E = 1.4426950408889634f;
    const float smin = fdec(g_smin_enc);
    const float smax = fdec(g_smax_enc);
    const float emax = fdec(g_emax_enc);
    const float c1 = L2E / (smax - smin);
    const float c0 = -smin * c1;
    const float c2 = L2E / emax;
    const float sthr = smin + 0.5f * (smax - smin);

    __shared__ float2 scol[8][128];

    float cp[8] = {0, 0, 0, 0, 0, 0, 0, 0};
    float cn[8] = {0, 0, 0, 0, 0, 0, 0, 0};
    float rp[8], rn[8];

    const char* base0 = (const char*)&g_se[(size_t)(i0 + w * 16 + rhalf) * BSZ + j0 + cg * 8];
    const size_t rstep = (size_t)2 * BSZ * 4;   // 2 rows per iteration, 4B per element

    uint4 v0 = ldg_nc4(base0);
    uint4 v1 = ldg_nc4(base0 + 16);

    #pragma unroll
    for (int it = 0; it < 8; it++) {
        uint4 a0 = v0, a1 = v1;
        if (it < 7) {
            const char* nb = base0 + (size_t)(it + 1) * rstep;
            v0 = ldg_nc4(nb);
            v1 = ldg_nc4(nb + 16);
        }
        unsigned uu[8] = {a0.x, a0.y, a0.z, a0.w, a1.x, a1.y, a1.z, a1.w};
        float p = 0.0f, n = 0.0f;
        #pragma unroll
        for (int x = 0; x < 8; x++) {
            float2 f = __half22float2(*(__half2*)&uu[x]);   // f.x = sim, f.y = eud
            float d = fmaf(f.y, c2, fmaf(f.x, c1, c0));
            bool pos = f.x > sthr;
            float val = ex2f(pos ? d : (L2E - d));
            float vp = pos ? val : 0.0f;
            float vn = pos ? 0.0f : val;
            p += vp; n += vn;
            cp[x] += vp; cn[x] += vn;
        }
        rp[it] = p;
        rn[it] = n;
    }

    // batched row reductions: 16 independent shfl chains pipeline through the unit
    #pragma unroll
    for (int off = 8; off; off >>= 1) {
        #pragma unroll
        for (int it = 0; it < 8; it++) {
            rp[it] += __shfl_xor_sync(0xffffffffu, rp[it], off);
            rn[it] += __shfl_xor_sync(0xffffffffu, rn[it], off);
        }
    }
    if (cg == 0) {
        #pragma unroll
        for (int it = 0; it < 8; it++) {
            int row = w * 16 + it * 2 + rhalf;
            g_part[(size_t)bj * BSZ + i0 + row] = make_float2(rp[it], rn[it]);
        }
    }

    // fold the two row-halves' column partials, then cross-warp reduce in smem
    #pragma unroll
    for (int x = 0; x < 8; x++) {
        cp[x] += __shfl_xor_sync(0xffffffffu, cp[x], 16);
        cn[x] += __shfl_xor_sync(0xffffffffu, cn[x], 16);
    }
    if (rhalf == 0) {
        #pragma unroll
        for (int x = 0; x < 8; x++) scol[w][cg * 8 + x] = make_float2(cp[x], cn[x]);
    }
    __syncthreads();
    if (bi != bj && t < 128) {
        float p = 0.0f, n = 0.0f;
        #pragma unroll
        for (int ww = 0; ww < 8; ww++) {
            float2 v = scol[ww][t];
            p += v.x; n += v.y;
        }
        g_part[(size_t)bi * BSZ + j0 + t] = make_float2(p, n);
    }
}

// ---------------- kernel 4: per-row reduce + fused final mean (ticket) ----------------
__global__ __launch_bounds__(256) void rowreduce_kernel(float* __restrict__ out) {
    const int w = threadIdx.x >> 5, lane = threadIdx.x & 31;
    const int row = blockIdx.x * 32 + lane;

    // warp w sums tiles w*8 .. w*8+7 for 32 consecutive rows (coalesced, MLP-8)
    float2 v[8];
    #pragma unroll
    for (int k = 0; k < 8; k++)
        v[k] = g_part[(size_t)(w * 8 + k) * BSZ + row];
    float P = 0.0f, N = 0.0f;
    #pragma unroll
    for (int k = 0; k < 8; k++) { P += v[k].x; N += v[k].y; }

    __shared__ float2 sc[8][32];
    sc[w][lane] = make_float2(P, N);
    __syncthreads();
    if (w == 0) {
        float Pt = 0.0f, Nt = 0.0f;
        #pragma unroll
        for (int ww = 0; ww < 8; ww++) {
            float2 u = sc[ww][lane];
            Pt += u.x; Nt += u.y;
        }
        float lp = fmaxf(logf(Pt), 0.0f);   // log(0) = -inf -> clamped to 0
        float ln = fmaxf(logf(Nt), 0.0f);
        g_rowloss[row] = lp + ln;
    }
    __syncthreads();

    // ticket: last block to finish reduces all rowloss deterministically
    __shared__ bool isLast;
    if (threadIdx.x == 0) {
        __threadfence();
        unsigned tk = atomicAdd(&g_ticket, 1u);
        isLast = (tk == gridDim.x - 1u);
    }
    __syncthreads();
    if (isLast) {
        const int t = threadIdx.x;
        __shared__ float s[256];
        float a = 0.0f;
        for (int i = t; i < BSZ; i += 256) a += g_rowloss[i];
        s[t] = a;
        __syncthreads();
        #pragma unroll
        for (int o = 128; o; o >>= 1) {
            if (t < o) s[t] += s[t + o];
            __syncthreads();
        }
        if (t == 0) out[0] = s[0] * (1.0f / (float)BSZ);
    }
}

// ---------------- launch ----------------
extern "C" void kernel_launch(void* const* d_in, const int* in_sizes, int n_in,
                              void* d_out, int out_size) {
    const float* outputs = (const float*)d_in[0];
    const float* labels  = (const float*)d_in[1];
    if (n_in >= 2 && in_sizes[0] == BSZ * CDIM && in_sizes[1] == BSZ * DDIM) {
        const float* tmp = outputs; outputs = labels; labels = tmp;
    }
    float* out = (float*)d_out;

    cudaFuncSetAttribute(gram_mma, cudaFuncAttributeMaxDynamicSharedMemorySize, SM_BYTES);

    rowprep_kernel<<<BSZ / 8, 256>>>(outputs, labels);
    gram_mma<<<NPAIRS, 256, SM_BYTES>>>();
    loss_tile_kernel<<<NPAIRS, 256>>>();
    rowreduce_kernel<<<BSZ / 32, 256>>>(out);
}

// round 16
// speedup vs baseline: 1.0185x; 1.0101x over previous
#include <cuda_runtime.h>
#include <cuda_fp16.h>
#include <cstdint>

#define BSZ 8192
#define CDIM 128
#define DDIM 256
#define TILE 128
#define NTILE 64          // BSZ / TILE
#define NPAIRS 2080       // NTILE*(NTILE+1)/2
#define NRBLK 256         // rowreduce grid (BSZ / 32)

// ---------------- scratch (static device globals; no allocation) ----------------
__device__ unsigned g_se[(size_t)BSZ * BSZ];    // packed (sim fp16 | eud fp16); upper tiles only
__device__ __half g_lab_h[(size_t)BSZ * CDIM];  // pre-normalized labels, fp16
__device__ __half g_out_h[(size_t)BSZ * DDIM];  // outputs, fp16
__device__ float g_sq[BSZ];                     // ||fp16(output_i)||^2 (fp32 accum)
__device__ float2 g_part[(size_t)NTILE * BSZ];  // per-(tile, row) partial sums (TILE-MAJOR)
__device__ float g_bpart[NRBLK];                // per-rowreduce-block loss partials
__device__ unsigned g_smin_enc, g_smax_enc, g_emax_enc;
__device__ unsigned g_ticket;

// monotone float <-> uint encoding so min/max reduce with integer atomics
__device__ __forceinline__ unsigned fenc(float f) {
    unsigned u = __float_as_uint(f);
    return (u & 0x80000000u) ? ~u : (u | 0x80000000u);
}
__device__ __forceinline__ float fdec(unsigned e) {
    unsigned u = (e & 0x80000000u) ? (e & 0x7FFFFFFFu) : ~e;
    return __uint_as_float(u);
}

// triangular pair decode: k in [0, NPAIRS) -> (a, b) with 0 <= a <= b < NTILE
__device__ __forceinline__ int tri_off(int a) { return a * NTILE - (a * (a - 1)) / 2; }
__device__ __forceinline__ void tri_decode(int k, int& a, int& b) {
    int aa = (int)((129.0f - sqrtf(16641.0f - 8.0f * (float)k)) * 0.5f);
    aa = max(0, min(63, aa));
    while (aa < 63 && tri_off(aa + 1) <= k) aa++;
    while (aa > 0 && tri_off(aa) > k) aa--;
    a = aa;
    b = aa + (k - tri_off(aa));
}

__device__ __forceinline__ uint32_t smem_u32(const void* p) {
    uint32_t a;
    asm("{ .reg .u64 t; cvta.to.shared.u64 t, %1; cvt.u32.u64 %0, t; }" : "=r"(a) : "l"(p));
    return a;
}
__device__ __forceinline__ uint4 ldsm_x4(uint32_t addr) {
    uint4 r;
    asm volatile("ldmatrix.sync.aligned.m8n8.x4.shared.b16 {%0,%1,%2,%3}, [%4];"
                 : "=r"(r.x), "=r"(r.y), "=r"(r.z), "=r"(r.w) : "r"(addr));
    return r;
}
__device__ __forceinline__ void mma16(float* c, uint4 a, uint32_t b0, uint32_t b1) {
    asm volatile(
        "mma.sync.aligned.m16n8k16.row.col.f32.f16.f16.f32 "
        "{%0,%1,%2,%3}, {%4,%5,%6,%7}, {%8,%9}, {%0,%1,%2,%3};"
        : "+f"(c[0]), "+f"(c[1]), "+f"(c[2]), "+f"(c[3])
        : "r"(a.x), "r"(a.y), "r"(a.z), "r"(a.w), "r"(b0), "r"(b1));
}
__device__ __forceinline__ float sqrtaf(float x) {
    float y;
    asm("sqrt.approx.f32 %0, %1;" : "=f"(y) : "f"(x));
    return y;
}
__device__ __forceinline__ uint4 ldg_nc4(const void* p) {
    uint4 r;
    asm volatile("ld.global.nc.v4.u32 {%0,%1,%2,%3}, [%4];"
                 : "=r"(r.x), "=r"(r.y), "=r"(r.z), "=r"(r.w) : "l"(p));
    return r;
}
#define CP_ASYNC16(dst, src) \
    asm volatile("cp.async.cg.shared.global [%0], [%1], 16;" :: "r"(dst), "l"(src))
#define CP_COMMIT() asm volatile("cp.async.commit_group;" ::: "memory")
#define CP_WAIT(n)  asm volatile("cp.async.wait_group %0;" :: "n"(n) : "memory")

// ---------------- gram smem layout (bytes): 3 stages x 32KB + sq arrays ----------------
#define OFF_SQI   98304
#define OFF_SQJ   98816
#define SM_BYTES  99328

// copy one 128-row x 64-half tile into SW128-swizzled smem via cp.async
__device__ __forceinline__ void cpasync_tile(const __half* __restrict__ src, int ldh, int k0,
                                             uint32_t smem_dst, int tid) {
    #pragma unroll
    for (int it = 0; it < 4; it++) {
        int e = tid + 256 * it;                  // 0..1023 granules of 16B
        int row = e >> 3, gq = e & 7;
        const __half* g = src + (size_t)row * ldh + k0 + gq * 8;
        uint32_t bo = (uint32_t)(row * 128 + gq * 16);
        uint32_t dst = smem_dst + (bo ^ ((bo >> 3) & 0x70));
        CP_ASYNC16(dst, g);
    }
}

__device__ __forceinline__ unsigned pack_se(unsigned simlo16, float e) {
    unsigned eh = (unsigned)__half_as_ushort(__float2half_rn(e));
    return (simlo16 & 0xFFFFu) | (eh << 16);
}

// ---------------- kernel 1: per-row prep (absorbs init; warp-per-row, no block syncs) ----------------
__global__ __launch_bounds__(256) void rowprep_kernel(const float* __restrict__ outputs,
                                                      const float* __restrict__ labels) {
    if (blockIdx.x == 0 && threadIdx.x == 0) {
        g_smin_enc = fenc(3.4e38f);
        g_smax_enc = fenc(-3.4e38f);
        g_emax_enc = fenc(0.0f);
        g_ticket = 0u;
    }

    const int row = blockIdx.x * 8 + (threadIdx.x >> 5);
    const int lane = threadIdx.x & 31;

    // labels: 4 elements per lane
    float l[4];
    float lsum = 0.0f;
    #pragma unroll
    for (int x = 0; x < 4; x++) {
        l[x] = labels[(size_t)row * CDIM + lane + 32 * x];
        lsum += l[x] * l[x];
    }
    #pragma unroll
    for (int off = 16; off; off >>= 1) lsum += __shfl_xor_sync(0xffffffffu, lsum, off);
    float invn = 1.0f / (sqrtf(lsum) + 1e-12f);
    #pragma unroll
    for (int x = 0; x < 4; x++)
        g_lab_h[(size_t)row * CDIM + lane + 32 * x] = __float2half(l[x] * invn);

    // outputs: 8 elements per lane; sq from rounded values
    float osum = 0.0f;
    #pragma unroll
    for (int x = 0; x < 8; x++) {
        float o = outputs[(size_t)row * DDIM + lane + 32 * x];
        __half h = __float2half(o);
        g_out_h[(size_t)row * DDIM + lane + 32 * x] = h;
        float f = __half2float(h);
        osum += f * f;
    }
    #pragma unroll
    for (int off = 16; off; off >>= 1) osum += __shfl_xor_sync(0xffffffffu, osum, off);
    if (lane == 0) g_sq[row] = osum;
}

// ---------------- kernel 2: fp16 mma fused grams, race-free 3-stage pipeline ----------------
__global__ __launch_bounds__(256, 2) void gram_mma() {
    int bi, bj;
    tri_decode(blockIdx.x, bi, bj);
    extern __shared__ float sm[];
    const uint32_t sb = smem_u32(sm);
    float* s_sqi = (float*)((char*)sm + OFF_SQI);
    float* s_sqj = (float*)((char*)sm + OFF_SQJ);

    const int tid = threadIdx.x;
    const int wid = tid >> 5, lane = tid & 31;
    const int warp_m = wid >> 2, warp_n = wid & 3;
    const int g = lane >> 2, tig = lane & 3;
    const int i0 = bi * TILE, j0 = bj * TILE;

    if (tid < 128) {
        s_sqi[tid] = g_sq[i0 + tid];
        s_sqj[tid] = g_sq[j0 + tid];
    }

    // ldmatrix per-lane address precompute (byte offsets within 128x64h tile, 128B rows)
    const int laneA_row = lane & 15;
    const uint32_t baseA = (uint32_t)(((warp_m * 64 + laneA_row) << 7) + ((lane >> 4) << 4));
    const uint32_t xorA = (uint32_t)((laneA_row & 7) << 4);
    const int rowB = warp_n * 32 + ((lane >> 4) << 3) + (lane & 7);
    const uint32_t baseB = (uint32_t)((rowB << 7) + (((lane >> 3) & 1) << 4));
    const uint32_t xorB = (uint32_t)((rowB & 7) << 4);

    float c[4][4][4];
    #pragma unroll
    for (int mf = 0; mf < 4; mf++)
        #pragma unroll
        for (int nf = 0; nf < 4; nf++)
            #pragma unroll
            for (int r = 0; r < 4; r++) c[mf][nf][r] = 0.0f;

    unsigned simh[32];   // register-resident sim tile (fp16x2)

    const __half* AiL = g_lab_h + (size_t)i0 * CDIM;
    const __half* BjL = g_lab_h + (size_t)j0 * CDIM;
    const __half* AiO = g_out_h + (size_t)i0 * DDIM;
    const __half* BjO = g_out_h + (size_t)j0 * DDIM;

    // preload chunks 0 and 1 (separate commit groups)
    cpasync_tile(AiL, CDIM, 0, sb, tid);
    cpasync_tile(BjL, CDIM, 0, sb + 16384, tid);
    CP_COMMIT();
    cpasync_tile(AiL, CDIM, 64, sb + 32768, tid);
    cpasync_tile(BjL, CDIM, 64, sb + 32768 + 16384, tid);
    CP_COMMIT();

    // merged 6-chunk pipeline: chunks 0-1 = label gram, 2-5 = output gram
    // order per iteration: WAIT(ch) -> sync -> prefetch(ch+2) -> compute(ch)
    #pragma unroll 1
    for (int ch = 0; ch < 6; ch++) {
        if (ch < 5) CP_WAIT(1);
        else        CP_WAIT(0);
        __syncthreads();

        if (ch + 2 < 6) {
            int nx = ch + 2;
            uint32_t nb = sb + (nx % 3) * 32768;
            if (nx < 2) {
                cpasync_tile(AiL, CDIM, nx * 64, nb, tid);
                cpasync_tile(BjL, CDIM, nx * 64, nb + 16384, tid);
            } else {
                cpasync_tile(AiO, DDIM, (nx - 2) * 64, nb, tid);
                cpasync_tile(BjO, DDIM, (nx - 2) * 64, nb + 16384, tid);
            }
            CP_COMMIT();
        }

        uint32_t sA = sb + (ch % 3) * 32768;
        uint32_t sB = sA + 16384;
        #pragma unroll
        for (int ks = 0; ks < 4; ks++) {
            uint4 a[4];
            #pragma unroll
            for (int mf = 0; mf < 4; mf++)
                a[mf] = ldsm_x4(sA + ((baseA + mf * 2048 + ks * 32) ^ xorA));
            uint4 b0 = ldsm_x4(sB + ((baseB + ks * 32) ^ xorB));
            uint4 b1 = ldsm_x4(sB + ((baseB + 2048 + ks * 32) ^ xorB));
            #pragma unroll
            for (int mf = 0; mf < 4; mf++) {
                mma16(c[mf][0], a[mf], b0.x, b0.y);
                mma16(c[mf][1], a[mf], b0.z, b0.w);
                mma16(c[mf][2], a[mf], b1.x, b1.y);
                mma16(c[mf][3], a[mf], b1.z, b1.w);
            }
        }
        if (ch == 1) {
            // epilogue A (overlaps in-flight copies): pack sim to regs, min/max, zero accums
            float lmin = 3.4e38f, lmax = -3.4e38f;
            #pragma unroll
            for (int mf = 0; mf < 4; mf++) {
                #pragma unroll
                for (int nf = 0; nf < 4; nf++) {
                    float v0 = c[mf][nf][0], v1 = c[mf][nf][1];
                    float v2 = c[mf][nf][2], v3 = c[mf][nf][3];
                    lmin = fminf(lmin, fminf(fminf(v0, v1), fminf(v2, v3)));
                    lmax = fmaxf(lmax, fmaxf(fmaxf(v0, v1), fmaxf(v2, v3)));
                    int idx0 = (mf * 4 + nf) * 2;
                    __half2 h01 = __floats2half2_rn(v0, v1);
                    __half2 h23 = __floats2half2_rn(v2, v3);
                    simh[idx0]     = *(unsigned*)&h01;
                    simh[idx0 + 1] = *(unsigned*)&h23;
                    c[mf][nf][0] = 0.0f; c[mf][nf][1] = 0.0f;
                    c[mf][nf][2] = 0.0f; c[mf][nf][3] = 0.0f;
                }
            }
            #pragma unroll
            for (int off = 16; off; off >>= 1) {
                lmin = fminf(lmin, __shfl_xor_sync(0xffffffffu, lmin, off));
                lmax = fmaxf(lmax, __shfl_xor_sync(0xffffffffu, lmax, off));
            }
            if (lane == 0) {
                atomicMin(&g_smin_enc, fenc(lmin));
                atomicMax(&g_smax_enc, fenc(lmax));
            }
        }
    }

    // epilogue B: eud + packed (sim|eud) store, upper tile only
    {
        float lemax = 0.0f;
        #pragma unroll
        for (int mf = 0; mf < 4; mf++) {
            int il = warp_m * 64 + mf * 16 + g;
            float q0 = s_sqi[il], q1 = s_sqi[il + 8];
            #pragma unroll
            for (int nf = 0; nf < 4; nf++) {
                int jl = warp_n * 32 + nf * 8 + 2 * tig;
                float r0 = s_sqj[jl], r1 = s_sqj[jl + 1];
                float d0 = q0 + r0 - 2.0f * c[mf][nf][0];
                float d1 = q0 + r1 - 2.0f * c[mf][nf][1];
                float d2_ = q1 + r0 - 2.0f * c[mf][nf][2];
                float d3 = q1 + r1 - 2.0f * c[mf][nf][3];
                float v0 = (d0 > 0.0f) ? sqrtaf(d0) : 0.0f;
                float v1 = (d1 > 0.0f) ? sqrtaf(d1) : 0.0f;
                float v2 = (d2_ > 0.0f) ? sqrtaf(d2_) : 0.0f;
                float v3 = (d3 > 0.0f) ? sqrtaf(d3) : 0.0f;
                if (i0 + il == j0 + jl) v0 = 0.0f;
                if (i0 + il == j0 + jl + 1) v1 = 0.0f;
                if (i0 + il + 8 == j0 + jl) v2 = 0.0f;
                if (i0 + il + 8 == j0 + jl + 1) v3 = 0.0f;
                lemax = fmaxf(lemax, fmaxf(fmaxf(v0, v1), fmaxf(v2, v3)));

                int idx0 = (mf * 4 + nf) * 2;
                unsigned sp01 = simh[idx0];
                unsigned sp23 = simh[idx0 + 1];
                unsigned u0 = pack_se(sp01, v0);
                unsigned u1 = pack_se(sp01 >> 16, v1);
                unsigned u2 = pack_se(sp23, v2);
                unsigned u3 = pack_se(sp23 >> 16, v3);

                *(uint2*)&g_se[(size_t)(i0 + il) * BSZ + j0 + jl]     = make_uint2(u0, u1);
                *(uint2*)&g_se[(size_t)(i0 + il + 8) * BSZ + j0 + jl] = make_uint2(u2, u3);
            }
        }
        #pragma unroll
        for (int off = 16; off; off >>= 1)
            lemax = fmaxf(lemax, __shfl_xor_sync(0xffffffffu, lemax, off));
        if (lane == 0) atomicMax(&g_emax_enc, fenc(lemax));
    }
}

// ---------------- kernel 3: tile loss — predicated accumulate, batched shfl ----------------
__global__ __launch_bounds__(256, 5) void loss_tile_kernel() {
    int bi, bj;
    tri_decode((int)blockIdx.x, bi, bj);
    const int i0 = bi * TILE, j0 = bj * TILE;
    const int t = threadIdx.x;
    const int w = t >> 5, lane = t & 31;
    const int cg = lane & 15;        // 8-column group: cols cg*8 .. cg*8+7
    const int rhalf = lane >> 4;     // row within the pair

    const float L2E = 1.4426950408889634f;
    const float smin = fdec(g_smin_enc);
    const float smax = fdec(g_smax_enc);
    const float emax = fdec(g_emax_enc);
    const float c1 = L2E / (smax - smin);
    const float c0 = -smin * c1;
    const float c2 = L2E / emax;
    const float sthr = smin + 0.5f * (smax - smin);

    __shared__ float2 scol[8][128];

    float cp[8] = {0, 0, 0, 0, 0, 0, 0, 0};
    float cn[8] = {0, 0, 0, 0, 0, 0, 0, 0};
    float rp[8], rn[8];

    const char* base0 = (const char*)&g_se[(size_t)(i0 + w * 16 + rhalf) * BSZ + j0 + cg * 8];
    const size_t rstep = (size_t)2 * BSZ * 4;   // 2 rows per iteration, 4B per element

    uint4 v0 = ldg_nc4(base0);
    uint4 v1 = ldg_nc4(base0 + 16);

    #pragma unroll
    for (int it = 0; it < 8; it++) {
        uint4 a0 = v0, a1 = v1;
        if (it < 7) {
            const char* nb = base0 + (size_t)(it + 1) * rstep;
            v0 = ldg_nc4(nb);
            v1 = ldg_nc4(nb + 16);
        }
        unsigned uu[8] = {a0.x, a0.y, a0.z, a0.w, a1.x, a1.y, a1.z, a1.w};
        float p = 0.0f, n = 0.0f;
        #pragma unroll
        for (int x = 0; x < 8; x++) {
            float2 f = __half22float2(*(__half2*)&uu[x]);   // f.x = sim, f.y = eud
            float d = fmaf(f.y, c2, fmaf(f.x, c1, c0));
            float dneg = L2E - d;
            // predicated: arg = pos ? d : L2E-d; val = 2^arg; pos ? {p,cp} : {n,cn} += val
            asm("{\n\t"
                ".reg .pred q;\n\t"
                ".reg .f32 a, v;\n\t"
                "setp.gt.f32 q, %4, %5;\n\t"
                "selp.f32 a, %6, %7, q;\n\t"
                "ex2.approx.f32 v, a;\n\t"
                "@q  add.f32 %0, %0, v;\n\t"
                "@!q add.f32 %1, %1, v;\n\t"
                "@q  add.f32 %2, %2, v;\n\t"
                "@!q add.f32 %3, %3, v;\n\t"
                "}"
                : "+f"(p), "+f"(n), "+f"(cp[x]), "+f"(cn[x])
                : "f"(f.x), "f"(sthr), "f"(d), "f"(dneg));
        }
        rp[it] = p;
        rn[it] = n;
    }

    // batched row reductions: 16 independent shfl chains pipeline through the unit
    #pragma unroll
    for (int off = 8; off; off >>= 1) {
        #pragma unroll
        for (int it = 0; it < 8; it++) {
            rp[it] += __shfl_xor_sync(0xffffffffu, rp[it], off);
            rn[it] += __shfl_xor_sync(0xffffffffu, rn[it], off);
        }
    }
    if (cg == 0) {
        #pragma unroll
        for (int it = 0; it < 8; it++) {
            int row = w * 16 + it * 2 + rhalf;
            g_part[(size_t)bj * BSZ + i0 + row] = make_float2(rp[it], rn[it]);
        }
    }

    // fold the two row-halves' column partials, then cross-warp reduce in smem
    #pragma unroll
    for (int x = 0; x < 8; x++) {
        cp[x] += __shfl_xor_sync(0xffffffffu, cp[x], 16);
        cn[x] += __shfl_xor_sync(0xffffffffu, cn[x], 16);
    }
    if (rhalf == 0) {
        #pragma unroll
        for (int x = 0; x < 8; x++) scol[w][cg * 8 + x] = make_float2(cp[x], cn[x]);
    }
    __syncthreads();
    if (bi != bj && t < 128) {
        float p = 0.0f, n = 0.0f;
        #pragma unroll
        for (int ww = 0; ww < 8; ww++) {
            float2 v = scol[ww][t];
            p += v.x; n += v.y;
        }
        g_part[(size_t)bi * BSZ + j0 + t] = make_float2(p, n);
    }
}

// ---------------- kernel 4: per-row reduce -> block partials -> fused final (ticket) ----------------
__global__ __launch_bounds__(256) void rowreduce_kernel(float* __restrict__ out) {
    const int w = threadIdx.x >> 5, lane = threadIdx.x & 31;
    const int row = blockIdx.x * 32 + lane;

    // warp w sums tiles w*8 .. w*8+7 for 32 consecutive rows (coalesced, MLP-8)
    float2 v[8];
    #pragma unroll
    for (int k = 0; k < 8; k++)
        v[k] = g_part[(size_t)(w * 8 + k) * BSZ + row];
    float P = 0.0f, N = 0.0f;
    #pragma unroll
    for (int k = 0; k < 8; k++) { P += v[k].x; N += v[k].y; }

    __shared__ float2 sc[8][32];
    sc[w][lane] = make_float2(P, N);
    __syncthreads();
    if (w == 0) {
        float Pt = 0.0f, Nt = 0.0f;
        #pragma unroll
        for (int ww = 0; ww < 8; ww++) {
            float2 u = sc[ww][lane];
            Pt += u.x; Nt += u.y;
        }
        float lp = fmaxf(logf(Pt), 0.0f);   // log(0) = -inf -> clamped to 0
        float ln = fmaxf(logf(Nt), 0.0f);
        float rl = lp + ln;
        // warp-reduce the 32 row losses into this block's partial (fixed order)
        #pragma unroll
        for (int off = 16; off; off >>= 1)
            rl += __shfl_xor_sync(0xffffffffu, rl, off);
        if (lane == 0) g_bpart[blockIdx.x] = rl;
    }
    __syncthreads();

    // ticket: last block reduces the 256 block partials deterministically
    __shared__ bool isLast;
    if (threadIdx.x == 0) {
        __threadfence();
        unsigned tk = atomicAdd(&g_ticket, 1u);
        isLast = (tk == gridDim.x - 1u);
    }
    __syncthreads();
    if (isLast) {
        const int t = threadIdx.x;
        __shared__ float s[256];
        s[t] = g_bpart[t];
        __syncthreads();
        #pragma unroll
        for (int o = 128; o; o >>= 1) {
            if (t < o) s[t] += s[t + o];
            __syncthreads();
        }
        if (t == 0) out[0] = s[0] * (1.0f / (float)BSZ);
    }
}

// ---------------- launch ----------------
extern "C" void kernel_launch(void* const* d_in, const int* in_sizes, int n_in,
                              void* d_out, int out_size) {
    const float* outputs = (const float*)d_in[0];
    const float* labels  = (const float*)d_in[1];
    if (n_in >= 2 && in_sizes[0] == BSZ * CDIM && in_sizes[1] == BSZ * DDIM) {
        const float* tmp = outputs; outputs = labels; labels = tmp;
    }
    float* out = (float*)d_out;

    cudaFuncSetAttribute(gram_mma, cudaFuncAttributeMaxDynamicSharedMemorySize, SM_BYTES);

    rowprep_kernel<<<BSZ / 8, 256>>>(outputs, labels);
    gram_mma<<<NPAIRS, 256, SM_BYTES>>>();
    loss_tile_kernel<<<NPAIRS, 256>>>();
    rowreduce_kernel<<<NRBLK, 256>>>(out);
}

// round 17
// speedup vs baseline: 1.0239x; 1.0053x over previous
#include <cuda_runtime.h>
#include <cuda_fp16.h>
#include <cstdint>

#define BSZ 8192
#define CDIM 128
#define DDIM 256
#define TILE 128
#define NTILE 64          // BSZ / TILE
#define NPAIRS 2080       // NTILE*(NTILE+1)/2
#define NRBLK 256         // rowreduce grid (BSZ / 32)

// ---------------- scratch (static device globals; no allocation) ----------------
__device__ unsigned g_se[(size_t)BSZ * BSZ];    // packed (sim fp16 | eud fp16); upper tiles only
__device__ __half g_lab_h[(size_t)BSZ * CDIM];  // pre-normalized labels, fp16
__device__ __half g_out_h[(size_t)BSZ * DDIM];  // outputs, fp16
__device__ float g_sq[BSZ];                     // ||fp16(output_i)||^2 (fp32 accum)
__device__ float2 g_part[(size_t)NTILE * BSZ];  // per-(tile, row) partial sums (TILE-MAJOR)
__device__ float g_bpart[NRBLK];                // per-rowreduce-block loss partials
__device__ unsigned g_smin_enc, g_smax_enc, g_emax_enc;
__device__ unsigned g_ticket;

// monotone float <-> uint encoding so min/max reduce with integer atomics
__device__ __forceinline__ unsigned fenc(float f) {
    unsigned u = __float_as_uint(f);
    return (u & 0x80000000u) ? ~u : (u | 0x80000000u);
}
__device__ __forceinline__ float fdec(unsigned e) {
    unsigned u = (e & 0x80000000u) ? (e & 0x7FFFFFFFu) : ~e;
    return __uint_as_float(u);
}

// triangular pair decode: k in [0, NPAIRS) -> (a, b) with 0 <= a <= b < NTILE
__device__ __forceinline__ int tri_off(int a) { return a * NTILE - (a * (a - 1)) / 2; }
__device__ __forceinline__ void tri_decode(int k, int& a, int& b) {
    int aa = (int)((129.0f - sqrtf(16641.0f - 8.0f * (float)k)) * 0.5f);
    aa = max(0, min(63, aa));
    while (aa < 63 && tri_off(aa + 1) <= k) aa++;
    while (aa > 0 && tri_off(aa) > k) aa--;
    a = aa;
    b = aa + (k - tri_off(aa));
}

__device__ __forceinline__ uint32_t smem_u32(const void* p) {
    uint32_t a;
    asm("{ .reg .u64 t; cvta.to.shared.u64 t, %1; cvt.u32.u64 %0, t; }" : "=r"(a) : "l"(p));
    return a;
}
__device__ __forceinline__ uint4 ldsm_x4(uint32_t addr) {
    uint4 r;
    asm volatile("ldmatrix.sync.aligned.m8n8.x4.shared.b16 {%0,%1,%2,%3}, [%4];"
                 : "=r"(r.x), "=r"(r.y), "=r"(r.z), "=r"(r.w) : "r"(addr));
    return r;
}
__device__ __forceinline__ void mma16(float* c, uint4 a, uint32_t b0, uint32_t b1) {
    asm volatile(
        "mma.sync.aligned.m16n8k16.row.col.f32.f16.f16.f32 "
        "{%0,%1,%2,%3}, {%4,%5,%6,%7}, {%8,%9}, {%0,%1,%2,%3};"
        : "+f"(c[0]), "+f"(c[1]), "+f"(c[2]), "+f"(c[3])
        : "r"(a.x), "r"(a.y), "r"(a.z), "r"(a.w), "r"(b0), "r"(b1));
}
__device__ __forceinline__ float sqrtaf(float x) {
    float y;
    asm("sqrt.approx.f32 %0, %1;" : "=f"(y) : "f"(x));
    return y;
}
__device__ __forceinline__ uint4 ldg_nc4(const void* p) {
    uint4 r;
    asm volatile("ld.global.nc.v4.u32 {%0,%1,%2,%3}, [%4];"
                 : "=r"(r.x), "=r"(r.y), "=r"(r.z), "=r"(r.w) : "l"(p));
    return r;
}
#define CP_ASYNC16(dst, src) \
    asm volatile("cp.async.cg.shared.global [%0], [%1], 16;" :: "r"(dst), "l"(src))
#define CP_COMMIT() asm volatile("cp.async.commit_group;" ::: "memory")
#define CP_WAIT(n)  asm volatile("cp.async.wait_group %0;" :: "n"(n) : "memory")

// ---------------- gram smem layout (bytes): 3 stages x 32KB + sq arrays ----------------
#define OFF_SQI   98304
#define OFF_SQJ   98816
#define SM_BYTES  99328

// copy one 128-row x 64-half tile into SW128-swizzled smem via cp.async
__device__ __forceinline__ void cpasync_tile(const __half* __restrict__ src, int ldh, int k0,
                                             uint32_t smem_dst, int tid) {
    #pragma unroll
    for (int it = 0; it < 4; it++) {
        int e = tid + 256 * it;                  // 0..1023 granules of 16B
        int row = e >> 3, gq = e & 7;
        const __half* g = src + (size_t)row * ldh + k0 + gq * 8;
        uint32_t bo = (uint32_t)(row * 128 + gq * 16);
        uint32_t dst = smem_dst + (bo ^ ((bo >> 3) & 0x70));
        CP_ASYNC16(dst, g);
    }
}

__device__ __forceinline__ unsigned pack_se(unsigned simlo16, float e) {
    unsigned eh = (unsigned)__half_as_ushort(__float2half_rn(e));
    return (simlo16 & 0xFFFFu) | (eh << 16);
}

// ---------------- kernel 1: per-row prep (absorbs init; warp-per-row, no block syncs) ----------------
__global__ __launch_bounds__(256) void rowprep_kernel(const float* __restrict__ outputs,
                                                      const float* __restrict__ labels) {
    if (blockIdx.x == 0 && threadIdx.x == 0) {
        g_smin_enc = fenc(3.4e38f);
        g_smax_enc = fenc(-3.4e38f);
        g_emax_enc = fenc(0.0f);
        g_ticket = 0u;
    }

    const int row = blockIdx.x * 8 + (threadIdx.x >> 5);
    const int lane = threadIdx.x & 31;

    // labels: 4 elements per lane
    float l[4];
    float lsum = 0.0f;
    #pragma unroll
    for (int x = 0; x < 4; x++) {
        l[x] = labels[(size_t)row * CDIM + lane + 32 * x];
        lsum += l[x] * l[x];
    }
    #pragma unroll
    for (int off = 16; off; off >>= 1) lsum += __shfl_xor_sync(0xffffffffu, lsum, off);
    float invn = 1.0f / (sqrtf(lsum) + 1e-12f);
    #pragma unroll
    for (int x = 0; x < 4; x++)
        g_lab_h[(size_t)row * CDIM + lane + 32 * x] = __float2half(l[x] * invn);

    // outputs: 8 elements per lane; sq from rounded values
    float osum = 0.0f;
    #pragma unroll
    for (int x = 0; x < 8; x++) {
        float o = outputs[(size_t)row * DDIM + lane + 32 * x];
        __half h = __float2half(o);
        g_out_h[(size_t)row * DDIM + lane + 32 * x] = h;
        float f = __half2float(h);
        osum += f * f;
    }
    #pragma unroll
    for (int off = 16; off; off >>= 1) osum += __shfl_xor_sync(0xffffffffu, osum, off);
    if (lane == 0) g_sq[row] = osum;
}

// ---------------- kernel 2: fp16 mma fused grams, race-free 3-stage pipeline ----------------
__global__ __launch_bounds__(256, 2) void gram_mma() {
    int bi, bj;
    tri_decode(blockIdx.x, bi, bj);
    extern __shared__ float sm[];
    const uint32_t sb = smem_u32(sm);
    float* s_sqi = (float*)((char*)sm + OFF_SQI);
    float* s_sqj = (float*)((char*)sm + OFF_SQJ);

    const int tid = threadIdx.x;
    const int wid = tid >> 5, lane = tid & 31;
    const int warp_m = wid >> 2, warp_n = wid & 3;
    const int g = lane >> 2, tig = lane & 3;
    const int i0 = bi * TILE, j0 = bj * TILE;

    if (tid < 128) {
        s_sqi[tid] = g_sq[i0 + tid];
        s_sqj[tid] = g_sq[j0 + tid];
    }

    // ldmatrix per-lane address precompute (byte offsets within 128x64h tile, 128B rows)
    const int laneA_row = lane & 15;
    const uint32_t baseA = (uint32_t)(((warp_m * 64 + laneA_row) << 7) + ((lane >> 4) << 4));
    const uint32_t xorA = (uint32_t)((laneA_row & 7) << 4);
    const int rowB = warp_n * 32 + ((lane >> 4) << 3) + (lane & 7);
    const uint32_t baseB = (uint32_t)((rowB << 7) + (((lane >> 3) & 1) << 4));
    const uint32_t xorB = (uint32_t)((rowB & 7) << 4);

    float c[4][4][4];
    #pragma unroll
    for (int mf = 0; mf < 4; mf++)
        #pragma unroll
        for (int nf = 0; nf < 4; nf++)
            #pragma unroll
            for (int r = 0; r < 4; r++) c[mf][nf][r] = 0.0f;

    unsigned simh[32];   // register-resident sim tile (fp16x2)

    const __half* AiL = g_lab_h + (size_t)i0 * CDIM;
    const __half* BjL = g_lab_h + (size_t)j0 * CDIM;
    const __half* AiO = g_out_h + (size_t)i0 * DDIM;
    const __half* BjO = g_out_h + (size_t)j0 * DDIM;

    // preload chunks 0 and 1 (separate commit groups)
    cpasync_tile(AiL, CDIM, 0, sb, tid);
    cpasync_tile(BjL, CDIM, 0, sb + 16384, tid);
    CP_COMMIT();
    cpasync_tile(AiL, CDIM, 64, sb + 32768, tid);
    cpasync_tile(BjL, CDIM, 64, sb + 32768 + 16384, tid);
    CP_COMMIT();

    // merged 6-chunk pipeline: chunks 0-1 = label gram, 2-5 = output gram
    // order per iteration: WAIT(ch) -> sync -> prefetch(ch+2) -> compute(ch)
    #pragma unroll 1
    for (int ch = 0; ch < 6; ch++) {
        if (ch < 5) CP_WAIT(1);
        else        CP_WAIT(0);
        __syncthreads();

        if (ch + 2 < 6) {
            int nx = ch + 2;
            uint32_t nb = sb + (nx % 3) * 32768;
            if (nx < 2) {
                cpasync_tile(AiL, CDIM, nx * 64, nb, tid);
                cpasync_tile(BjL, CDIM, nx * 64, nb + 16384, tid);
            } else {
                cpasync_tile(AiO, DDIM, (nx - 2) * 64, nb, tid);
                cpasync_tile(BjO, DDIM, (nx - 2) * 64, nb + 16384, tid);
            }
            CP_COMMIT();
        }

        uint32_t sA = sb + (ch % 3) * 32768;
        uint32_t sB = sA + 16384;
        #pragma unroll
        for (int ks = 0; ks < 4; ks++) {
            uint4 a[4];
            #pragma unroll
            for (int mf = 0; mf < 4; mf++)
                a[mf] = ldsm_x4(sA + ((baseA + mf * 2048 + ks * 32) ^ xorA));
            uint4 b0 = ldsm_x4(sB + ((baseB + ks * 32) ^ xorB));
            uint4 b1 = ldsm_x4(sB + ((baseB + 2048 + ks * 32) ^ xorB));
            #pragma unroll
            for (int mf = 0; mf < 4; mf++) {
                mma16(c[mf][0], a[mf], b0.x, b0.y);
                mma16(c[mf][1], a[mf], b0.z, b0.w);
                mma16(c[mf][2], a[mf], b1.x, b1.y);
                mma16(c[mf][3], a[mf], b1.z, b1.w);
            }
        }
        if (ch == 1) {
            // epilogue A (overlaps in-flight copies): pack sim to regs, min/max, zero accums
            float lmin = 3.4e38f, lmax = -3.4e38f;
            #pragma unroll
            for (int mf = 0; mf < 4; mf++) {
                #pragma unroll
                for (int nf = 0; nf < 4; nf++) {
                    float v0 = c[mf][nf][0], v1 = c[mf][nf][1];
                    float v2 = c[mf][nf][2], v3 = c[mf][nf][3];
                    lmin = fminf(lmin, fminf(fminf(v0, v1), fminf(v2, v3)));
                    lmax = fmaxf(lmax, fmaxf(fmaxf(v0, v1), fmaxf(v2, v3)));
                    int idx0 = (mf * 4 + nf) * 2;
                    __half2 h01 = __floats2half2_rn(v0, v1);
                    __half2 h23 = __floats2half2_rn(v2, v3);
                    simh[idx0]     = *(unsigned*)&h01;
                    simh[idx0 + 1] = *(unsigned*)&h23;
                    c[mf][nf][0] = 0.0f; c[mf][nf][1] = 0.0f;
                    c[mf][nf][2] = 0.0f; c[mf][nf][3] = 0.0f;
                }
            }
            #pragma unroll
            for (int off = 16; off; off >>= 1) {
                lmin = fminf(lmin, __shfl_xor_sync(0xffffffffu, lmin, off));
                lmax = fmaxf(lmax, __shfl_xor_sync(0xffffffffu, lmax, off));
            }
            if (lane == 0) {
                atomicMin(&g_smin_enc, fenc(lmin));
                atomicMax(&g_smax_enc, fenc(lmax));
            }
        }
    }

    // epilogue B: eud + packed (sim|eud) store, upper tile only
    {
        float lemax = 0.0f;
        #pragma unroll
        for (int mf = 0; mf < 4; mf++) {
            int il = warp_m * 64 + mf * 16 + g;
            float q0 = s_sqi[il], q1 = s_sqi[il + 8];
            #pragma unroll
            for (int nf = 0; nf < 4; nf++) {
                int jl = warp_n * 32 + nf * 8 + 2 * tig;
                float r0 = s_sqj[jl], r1 = s_sqj[jl + 1];
                float d0 = q0 + r0 - 2.0f * c[mf][nf][0];
                float d1 = q0 + r1 - 2.0f * c[mf][nf][1];
                float d2_ = q1 + r0 - 2.0f * c[mf][nf][2];
                float d3 = q1 + r1 - 2.0f * c[mf][nf][3];
                float v0 = (d0 > 0.0f) ? sqrtaf(d0) : 0.0f;
                float v1 = (d1 > 0.0f) ? sqrtaf(d1) : 0.0f;
                float v2 = (d2_ > 0.0f) ? sqrtaf(d2_) : 0.0f;
                float v3 = (d3 > 0.0f) ? sqrtaf(d3) : 0.0f;
                if (i0 + il == j0 + jl) v0 = 0.0f;
                if (i0 + il == j0 + jl + 1) v1 = 0.0f;
                if (i0 + il + 8 == j0 + jl) v2 = 0.0f;
                if (i0 + il + 8 == j0 + jl + 1) v3 = 0.0f;
                lemax = fmaxf(lemax, fmaxf(fmaxf(v0, v1), fmaxf(v2, v3)));

                int idx0 = (mf * 4 + nf) * 2;
                unsigned sp01 = simh[idx0];
                unsigned sp23 = simh[idx0 + 1];
                unsigned u0 = pack_se(sp01, v0);
                unsigned u1 = pack_se(sp01 >> 16, v1);
                unsigned u2 = pack_se(sp23, v2);
                unsigned u3 = pack_se(sp23 >> 16, v3);

                *(uint2*)&g_se[(size_t)(i0 + il) * BSZ + j0 + jl]     = make_uint2(u0, u1);
                *(uint2*)&g_se[(size_t)(i0 + il + 8) * BSZ + j0 + jl] = make_uint2(u2, u3);
            }
        }
        #pragma unroll
        for (int off = 16; off; off >>= 1)
            lemax = fmaxf(lemax, __shfl_xor_sync(0xffffffffu, lemax, off));
        if (lane == 0) atomicMax(&g_emax_enc, fenc(lemax));
    }
}

// ---------------- kernel 3: tile loss — fp16x2 SIMD math, batched shfl ----------------
__global__ __launch_bounds__(256, 5) void loss_tile_kernel() {
    int bi, bj;
    tri_decode((int)blockIdx.x, bi, bj);
    const int i0 = bi * TILE, j0 = bj * TILE;
    const int t = threadIdx.x;
    const int w = t >> 5, lane = t & 31;
    const int cg = lane & 15;        // 8-column group: cols cg*8 .. cg*8+7
    const int rhalf = lane >> 4;     // row within the pair

    const float L2E = 1.4426950408889634f;
    const float smin = fdec(g_smin_enc);
    const float smax = fdec(g_smax_enc);
    const float emax = fdec(g_emax_enc);
    const float c1 = L2E / (smax - smin);
    const float c0 = -smin * c1;
    const float c2 = L2E / emax;
    const float sthr = smin + 0.5f * (smax - smin);

    const __half2 c0h = __float2half2_rn(c0);
    const __half2 c1h = __float2half2_rn(c1);
    const __half2 c2h = __float2half2_rn(c2);
    const __half2 sthrh = __float2half2_rn(sthr);
    const __half2 l2eh = __float2half2_rn(L2E);

    __shared__ float2 scol[8][128];

    __half2 cph[4], cnh[4];
    #pragma unroll
    for (int x = 0; x < 4; x++) {
        cph[x] = __float2half2_rn(0.0f);
        cnh[x] = __float2half2_rn(0.0f);
    }
    float rp[8], rn[8];

    const char* base0 = (const char*)&g_se[(size_t)(i0 + w * 16 + rhalf) * BSZ + j0 + cg * 8];
    const size_t rstep = (size_t)2 * BSZ * 4;   // 2 rows per iteration, 4B per element

    uint4 v0 = ldg_nc4(base0);
    uint4 v1 = ldg_nc4(base0 + 16);

    #pragma unroll
    for (int it = 0; it < 8; it++) {
        uint4 a0 = v0, a1 = v1;
        if (it < 7) {
            const char* nb = base0 + (size_t)(it + 1) * rstep;
            v0 = ldg_nc4(nb);
            v1 = ldg_nc4(nb + 16);
        }
        unsigned uu[8] = {a0.x, a0.y, a0.z, a0.w, a1.x, a1.y, a1.z, a1.w};
        __half2 pacc = __float2half2_rn(0.0f);
        __half2 nacc = __float2half2_rn(0.0f);
        #pragma unroll
        for (int xp = 0; xp < 4; xp++) {
            unsigned ua = uu[2 * xp], ub = uu[2 * xp + 1];
            unsigned spk, epk;
            asm("prmt.b32 %0, %1, %2, 0x5410;" : "=r"(spk) : "r"(ua), "r"(ub));
            asm("prmt.b32 %0, %1, %2, 0x7632;" : "=r"(epk) : "r"(ua), "r"(ub));
            __half2 s2 = *(__half2*)&spk;
            __half2 e2 = *(__half2*)&epk;
            __half2 d2 = __hfma2(e2, c2h, __hfma2(s2, c1h, c0h));
            __half2 m2 = __hgt2(s2, sthrh);               // 1.0 / 0.0 mask
            __half2 dd = __hsub2(__hadd2(d2, d2), l2eh);  // 2d - L2E
            __half2 ba = __hsub2(l2eh, d2);               // L2E - d
            __half2 v2 = h2exp2(__hfma2(m2, dd, ba));     // 2^(pos ? d : L2E-d)
            __half2 pv = __hmul2(v2, m2);
            __half2 nv = __hsub2(v2, pv);
            pacc = __hadd2(pacc, pv);
            nacc = __hadd2(nacc, nv);
            cph[xp] = __hadd2(cph[xp], pv);
            cnh[xp] = __hadd2(cnh[xp], nv);
        }
        float2 pf = __half22float2(pacc);
        float2 nf = __half22float2(nacc);
        rp[it] = pf.x + pf.y;
        rn[it] = nf.x + nf.y;
    }

    // batched row reductions: 16 independent shfl chains pipeline through the unit
    #pragma unroll
    for (int off = 8; off; off >>= 1) {
        #pragma unroll
        for (int it = 0; it < 8; it++) {
            rp[it] += __shfl_xor_sync(0xffffffffu, rp[it], off);
            rn[it] += __shfl_xor_sync(0xffffffffu, rn[it], off);
        }
    }
    if (cg == 0) {
        #pragma unroll
        for (int it = 0; it < 8; it++) {
            int row = w * 16 + it * 2 + rhalf;
            g_part[(size_t)bj * BSZ + i0 + row] = make_float2(rp[it], rn[it]);
        }
    }

    // convert half2 col accumulators to fp32, fold row-halves, cross-warp reduce
    float cp[8], cn[8];
    #pragma unroll
    for (int x = 0; x < 4; x++) {
        float2 pf = __half22float2(cph[x]);
        float2 nf = __half22float2(cnh[x]);
        cp[2 * x] = pf.x; cp[2 * x + 1] = pf.y;
        cn[2 * x] = nf.x; cn[2 * x + 1] = nf.y;
    }
    #pragma unroll
    for (int x = 0; x < 8; x++) {
        cp[x] += __shfl_xor_sync(0xffffffffu, cp[x], 16);
        cn[x] += __shfl_xor_sync(0xffffffffu, cn[x], 16);
    }
    if (rhalf == 0) {
        #pragma unroll
        for (int x = 0; x < 8; x++) scol[w][cg * 8 + x] = make_float2(cp[x], cn[x]);
    }
    __syncthreads();
    if (bi != bj && t < 128) {
        float p = 0.0f, n = 0.0f;
        #pragma unroll
        for (int ww = 0; ww < 8; ww++) {
            float2 v = scol[ww][t];
            p += v.x; n += v.y;
        }
        g_part[(size_t)bi * BSZ + j0 + t] = make_float2(p, n);
    }
}

// ---------------- kernel 4: per-row reduce (16 warps) -> block partials -> fused final ----------------
__global__ __launch_bounds__(512) void rowreduce_kernel(float* __restrict__ out) {
    const int w = threadIdx.x >> 5, lane = threadIdx.x & 31;   // w in 0..15
    const int row = blockIdx.x * 32 + lane;

    // warp w sums tiles w*4 .. w*4+3 for 32 consecutive rows (coalesced, MLP-4)
    float2 v[4];
    #pragma unroll
    for (int k = 0; k < 4; k++)
        v[k] = g_part[(size_t)(w * 4 + k) * BSZ + row];
    float P = 0.0f, N = 0.0f;
    #pragma unroll
    for (int k = 0; k < 4; k++) { P += v[k].x; N += v[k].y; }

    __shared__ float2 sc[16][32];
    sc[w][lane] = make_float2(P, N);
    __syncthreads();
    if (w == 0) {
        float Pt = 0.0f, Nt = 0.0f;
        #pragma unroll
        for (int ww = 0; ww < 16; ww++) {
            float2 u = sc[ww][lane];
            Pt += u.x; Nt += u.y;
        }
        float lp = fmaxf(logf(Pt), 0.0f);   // log(0) = -inf -> clamped to 0
        float ln = fmaxf(logf(Nt), 0.0f);
        float rl = lp + ln;
        #pragma unroll
        for (int off = 16; off; off >>= 1)
            rl += __shfl_xor_sync(0xffffffffu, rl, off);
        if (lane == 0) g_bpart[blockIdx.x] = rl;
    }
    __syncthreads();

    // ticket: last block reduces the 256 block partials deterministically
    __shared__ bool isLast;
    if (threadIdx.x == 0) {
        __threadfence();
        unsigned tk = atomicAdd(&g_ticket, 1u);
        isLast = (tk == gridDim.x - 1u);
    }
    __syncthreads();
    if (isLast) {
        const int t = threadIdx.x;
        __shared__ float s[256];
        if (t < 256) s[t] = g_bpart[t];
        __syncthreads();
        #pragma unroll
        for (int o = 128; o; o >>= 1) {
            if (t < o) s[t] += s[t + o];
            __syncthreads();
        }
        if (t == 0) out[0] = s[0] * (1.0f / (float)BSZ);
    }
}

// ---------------- launch ----------------
extern "C" void kernel_launch(void* const* d_in, const int* in_sizes, int n_in,
                              void* d_out, int out_size) {
    const float* outputs = (const float*)d_in[0];
    const float* labels  = (const float*)d_in[1];
    if (n_in >= 2 && in_sizes[0] == BSZ * CDIM && in_sizes[1] == BSZ * DDIM) {
        const float* tmp = outputs; outputs = labels; labels = tmp;
    }
    float* out = (float*)d_out;

    cudaFuncSetAttribute(gram_mma, cudaFuncAttributeMaxDynamicSharedMemorySize, SM_BYTES);

    rowprep_kernel<<<BSZ / 8, 256>>>(outputs, labels);
    gram_mma<<<NPAIRS, 256, SM_BYTES>>>();
    loss_tile_kernel<<<NPAIRS, 256>>>();
    rowreduce_kernel<<<NRBLK, 512>>>(out);
}